// round 2
// baseline (speedup 1.0000x reference)
#include <cuda_runtime.h>
#include <cstdint>
#include <cstddef>

#define T_TOK 4096
#define DMODEL 512
#define NHEAD 8
#define HDIM 64
#define FDIM 2048
#define NLAYER 6
#define SEQ 2048

// ---------------- scratch (static device globals; no allocation) ----------------
__device__ float g_h[T_TOK * DMODEL];
__device__ float g_q[T_TOK * DMODEL];
__device__ float g_k[T_TOK * DMODEL];
__device__ float g_v[T_TOK * DMODEL];
__device__ float g_att[T_TOK * DMODEL];
__device__ float g_proj[T_TOK * DMODEL];
__device__ float g_ff[T_TOK * FDIM];

// ---------------- embedding: h[t,:] = emb[src[t],:] * sqrt(512) ----------------
// NOTE: src is int32 (JAX default config downgrades int64 -> int32)
__global__ __launch_bounds__(128) void embed_kernel(
    const int* __restrict__ src, const float* __restrict__ emb,
    float* __restrict__ h)
{
    int t = blockIdx.x;
    int tok = src[t];
    const float4* e = (const float4*)(emb + (size_t)tok * DMODEL);
    float4* o = (float4*)(h + (size_t)t * DMODEL);
    const float s = 22.627416997969522f;  // sqrt(512)
    float4 v = e[threadIdx.x];
    v.x *= s; v.y *= s; v.z *= s; v.w *= s;
    o[threadIdx.x] = v;
}

// ---------------- QKV: per-head shared 64x64 projections ----------------
// rows r = t*8 + head  (memory-contiguous 64-float slices of h)
__global__ __launch_bounds__(128) void qkv_kernel(
    const float* __restrict__ h,
    const float* __restrict__ Wq, const float* __restrict__ Wk, const float* __restrict__ Wv,
    const float* __restrict__ bq, const float* __restrict__ bk, const float* __restrict__ bv,
    float* __restrict__ Q, float* __restrict__ K, float* __restrict__ V)
{
    __shared__ float Ws[3][HDIM * HDIM];   // 48KB exactly
    int tid = threadIdx.x;
    for (int i = tid; i < HDIM * HDIM; i += 128) {
        Ws[0][i] = Wq[i];
        Ws[1][i] = Wk[i];
        Ws[2][i] = Wv[i];
    }
    __syncthreads();

    size_t r = (size_t)blockIdx.x * 128 + tid;   // 0..32767
    float4 x[16];
    const float4* xp = (const float4*)(h + r * HDIM);
#pragma unroll
    for (int i = 0; i < 16; i++) x[i] = xp[i];

#pragma unroll
    for (int m = 0; m < 3; m++) {
        const float* W = Ws[m];
        const float* bias = (m == 0) ? bq : ((m == 1) ? bk : bv);
        float* outp = ((m == 0) ? Q : ((m == 1) ? K : V)) + r * HDIM;
        for (int e0 = 0; e0 < HDIM; e0 += 4) {
            float acc[4] = {0.f, 0.f, 0.f, 0.f};
#pragma unroll
            for (int c = 0; c < 4; c++) {
                const float4* w4 = (const float4*)(W + (e0 + c) * HDIM);
#pragma unroll
                for (int i = 0; i < 16; i++) {
                    float4 w = w4[i];
                    acc[c] += x[i].x * w.x + x[i].y * w.y + x[i].z * w.z + x[i].w * w.w;
                }
            }
            float4 ov;
            ov.x = acc[0] + bias[e0 + 0];
            ov.y = acc[1] + bias[e0 + 1];
            ov.z = acc[2] + bias[e0 + 2];
            ov.w = acc[3] + bias[e0 + 3];
            *(float4*)(outp + e0) = ov;
        }
    }
}

// ---------------- flash attention (fp32, online softmax) ----------------
// block: one (n, head, 128-row q tile); 256 threads; 16 kv-tiles of 128
#define F_LDT 132  // padded smem leading dim (multiple of 4 for float4)

__global__ __launch_bounds__(256) void flash_kernel(
    const float* __restrict__ Q, const float* __restrict__ Kg,
    const float* __restrict__ Vg, const int* __restrict__ mask,
    float* __restrict__ Og)
{
    extern __shared__ float sm[];
    float* Qt   = sm;                       // [64][132]   d-major
    float* Kt   = Qt + 64 * F_LDT;          // [64][132]   d-major
    float* Vs   = Kt + 64 * F_LDT;          // [128][64]   k-major
    float* Pt   = Vs + 128 * 64;            // [128][132]  kcol-major
    float* mrow = Pt + 128 * F_LDT;         // [128]
    float* crow = mrow + 128;               // [128]
    float* lrow = crow + 128;               // [128]
    float* red  = lrow + 128;               // [128][16]
    float* mkv  = red + 2048;               // [128]

    int tid = threadIdx.x;
    int tx = tid & 15, ty = tid >> 4;
    int qt = blockIdx.x, hh = blockIdx.y, n = blockIdx.z;
    int q0 = qt * 128;
    size_t baseQ = ((size_t)(n * SEQ + q0)) * DMODEL + hh * HDIM;

    // load Q tile transposed: Qt[d][row]
#pragma unroll
    for (int it = 0; it < 8; ++it) {
        int lin = tid + it * 256;
        int row = lin >> 4, e4 = lin & 15;
        float4 v = *(const float4*)(Q + baseQ + (size_t)row * DMODEL + e4 * 4);
        Qt[(e4 * 4 + 0) * F_LDT + row] = v.x;
        Qt[(e4 * 4 + 1) * F_LDT + row] = v.y;
        Qt[(e4 * 4 + 2) * F_LDT + row] = v.z;
        Qt[(e4 * 4 + 3) * F_LDT + row] = v.w;
    }
    if (tid < 128) { mrow[tid] = -3.0e38f; lrow[tid] = 0.f; }

    float o[8][4];
#pragma unroll
    for (int i = 0; i < 8; i++)
#pragma unroll
        for (int j = 0; j < 4; j++) o[i][j] = 0.f;
    __syncthreads();   // A

    const float INV    = 0.04419417382415922f;        // 1/sqrt(512)
    const float MASKED = -1e10f * 0.04419417382415922f;

    for (int kt = 0; kt < 16; ++kt) {
        int k0 = kt * 128;
        size_t baseK = ((size_t)(n * SEQ + k0)) * DMODEL + hh * HDIM;
#pragma unroll
        for (int it = 0; it < 8; ++it) {
            int lin = tid + it * 256;
            int row = lin >> 4, e4 = lin & 15;
            float4 kv = *(const float4*)(Kg + baseK + (size_t)row * DMODEL + e4 * 4);
            Kt[(e4 * 4 + 0) * F_LDT + row] = kv.x;
            Kt[(e4 * 4 + 1) * F_LDT + row] = kv.y;
            Kt[(e4 * 4 + 2) * F_LDT + row] = kv.z;
            Kt[(e4 * 4 + 3) * F_LDT + row] = kv.w;
            float4 vv = *(const float4*)(Vg + baseK + (size_t)row * DMODEL + e4 * 4);
            *(float4*)&Vs[row * 64 + e4 * 4] = vv;
        }
        if (tid < 128) mkv[tid] = (float)mask[n * SEQ + k0 + tid];
        __syncthreads();   // loads visible

        // ---- S = Q @ K^T (128x128) ----
        float s[8][8];
#pragma unroll
        for (int i = 0; i < 8; i++)
#pragma unroll
            for (int j = 0; j < 8; j++) s[i][j] = 0.f;

#pragma unroll 8
        for (int d = 0; d < 64; ++d) {
            float4 a0 = *(const float4*)&Qt[d * F_LDT + ty * 8];
            float4 a1 = *(const float4*)&Qt[d * F_LDT + ty * 8 + 4];
            float4 b0 = *(const float4*)&Kt[d * F_LDT + tx * 8];
            float4 b1 = *(const float4*)&Kt[d * F_LDT + tx * 8 + 4];
            float a[8] = {a0.x, a0.y, a0.z, a0.w, a1.x, a1.y, a1.z, a1.w};
            float b[8] = {b0.x, b0.y, b0.z, b0.w, b1.x, b1.y, b1.z, b1.w};
#pragma unroll
            for (int i = 0; i < 8; i++)
#pragma unroll
                for (int j = 0; j < 8; j++) s[i][j] = fmaf(a[i], b[j], s[i][j]);
        }

        // mask + scale (matches ref: mask first, then /sqrt(D))
#pragma unroll
        for (int j = 0; j < 8; j++) {
            float mk = mkv[tx * 8 + j];
#pragma unroll
            for (int i = 0; i < 8; i++)
                s[i][j] = (mk == 0.f) ? MASKED : s[i][j] * INV;
        }

        // ---- online softmax: row max ----
#pragma unroll
        for (int i = 0; i < 8; i++) {
            float pm = s[i][0];
#pragma unroll
            for (int j = 1; j < 8; j++) pm = fmaxf(pm, s[i][j]);
            red[(ty * 8 + i) * 16 + tx] = pm;
        }
        __syncthreads();   // B
        if (tid < 128) {
            float mo = mrow[tid], mx = mo;
#pragma unroll
            for (int t = 0; t < 16; t++) mx = fmaxf(mx, red[tid * 16 + t]);
            crow[tid] = __expf(mo - mx);
            mrow[tid] = mx;
        }
        __syncthreads();   // C

        // ---- P = exp(s - m), transposed store; partial row sums ----
#pragma unroll
        for (int i = 0; i < 8; i++) {
            int row = ty * 8 + i;
            float mr = mrow[row];
            float ps = 0.f;
#pragma unroll
            for (int j = 0; j < 8; j++) {
                float p = __expf(s[i][j] - mr);
                ps += p;
                Pt[(tx * 8 + j) * F_LDT + row] = p;
            }
            red[row * 16 + tx] = ps;
        }
        // rescale O accumulators (crow valid after sync C)
#pragma unroll
        for (int i = 0; i < 8; i++) {
            float c = crow[ty * 8 + i];
#pragma unroll
            for (int j = 0; j < 4; j++) o[i][j] *= c;
        }
        __syncthreads();   // D  (Pt + red visible)
        if (tid < 128) {
            float s2 = 0.f;
#pragma unroll
            for (int t = 0; t < 16; t++) s2 += red[tid * 16 + t];
            lrow[tid] = lrow[tid] * crow[tid] + s2;
        }

        // ---- O += P @ V ----
#pragma unroll 8
        for (int kk = 0; kk < 128; ++kk) {
            float4 a0 = *(const float4*)&Pt[kk * F_LDT + ty * 8];
            float4 a1 = *(const float4*)&Pt[kk * F_LDT + ty * 8 + 4];
            float4 bv = *(const float4*)&Vs[kk * 64 + tx * 4];
            float a[8] = {a0.x, a0.y, a0.z, a0.w, a1.x, a1.y, a1.z, a1.w};
            float b[4] = {bv.x, bv.y, bv.z, bv.w};
#pragma unroll
            for (int i = 0; i < 8; i++)
#pragma unroll
                for (int j = 0; j < 4; j++) o[i][j] = fmaf(a[i], b[j], o[i][j]);
        }
        __syncthreads();   // E
    }

    // epilogue: divide by l, write out[n, q, h, d]
#pragma unroll
    for (int i = 0; i < 8; i++) {
        int row = ty * 8 + i;
        float linv = 1.f / lrow[row];
        float4 r;
        r.x = o[i][0] * linv;
        r.y = o[i][1] * linv;
        r.z = o[i][2] * linv;
        r.w = o[i][3] * linv;
        *(float4*)(Og + baseQ + (size_t)row * DMODEL + tx * 4) = r;
    }
}

// ---------------- tiled SGEMM: C[M,N] = A[M,K] @ B[N,K]^T + bias (opt ReLU) ----------------
template <bool RELU>
__global__ __launch_bounds__(256) void sgemm_bias_kernel(
    const float* __restrict__ A, const float* __restrict__ B,
    const float* __restrict__ bias, float* __restrict__ C,
    int M, int N, int K)
{
    __shared__ float Ast[16 * 132];
    __shared__ float Bst[16 * 132];
    int tid = threadIdx.x;
    int tx = tid & 15, ty = tid >> 4;
    int n0 = blockIdx.x * 128, m0 = blockIdx.y * 128;

    float acc[8][8];
#pragma unroll
    for (int i = 0; i < 8; i++)
#pragma unroll
        for (int j = 0; j < 8; j++) acc[i][j] = 0.f;

    for (int kb = 0; kb < K; kb += 16) {
#pragma unroll
        for (int it = 0; it < 2; ++it) {
            int lin = tid + it * 256;
            int row = lin >> 2, k4 = lin & 3;
            float4 av = *(const float4*)(A + (size_t)(m0 + row) * K + kb + k4 * 4);
            Ast[(k4 * 4 + 0) * 132 + row] = av.x;
            Ast[(k4 * 4 + 1) * 132 + row] = av.y;
            Ast[(k4 * 4 + 2) * 132 + row] = av.z;
            Ast[(k4 * 4 + 3) * 132 + row] = av.w;
            float4 bv = *(const float4*)(B + (size_t)(n0 + row) * K + kb + k4 * 4);
            Bst[(k4 * 4 + 0) * 132 + row] = bv.x;
            Bst[(k4 * 4 + 1) * 132 + row] = bv.y;
            Bst[(k4 * 4 + 2) * 132 + row] = bv.z;
            Bst[(k4 * 4 + 3) * 132 + row] = bv.w;
        }
        __syncthreads();
#pragma unroll
        for (int k = 0; k < 16; k++) {
            float4 a0 = *(const float4*)&Ast[k * 132 + ty * 8];
            float4 a1 = *(const float4*)&Ast[k * 132 + ty * 8 + 4];
            float4 b0 = *(const float4*)&Bst[k * 132 + tx * 8];
            float4 b1 = *(const float4*)&Bst[k * 132 + tx * 8 + 4];
            float a[8] = {a0.x, a0.y, a0.z, a0.w, a1.x, a1.y, a1.z, a1.w};
            float b[8] = {b0.x, b0.y, b0.z, b0.w, b1.x, b1.y, b1.z, b1.w};
#pragma unroll
            for (int i = 0; i < 8; i++)
#pragma unroll
                for (int j = 0; j < 8; j++) acc[i][j] = fmaf(a[i], b[j], acc[i][j]);
        }
        __syncthreads();
    }

    float bb[8];
#pragma unroll
    for (int j = 0; j < 8; j++) bb[j] = bias[n0 + tx * 8 + j];
#pragma unroll
    for (int i = 0; i < 8; i++) {
        int row = m0 + ty * 8 + i;
        float4 v0, v1;
        v0.x = acc[i][0] + bb[0]; v0.y = acc[i][1] + bb[1];
        v0.z = acc[i][2] + bb[2]; v0.w = acc[i][3] + bb[3];
        v1.x = acc[i][4] + bb[4]; v1.y = acc[i][5] + bb[5];
        v1.z = acc[i][6] + bb[6]; v1.w = acc[i][7] + bb[7];
        if (RELU) {
            v0.x = fmaxf(v0.x, 0.f); v0.y = fmaxf(v0.y, 0.f);
            v0.z = fmaxf(v0.z, 0.f); v0.w = fmaxf(v0.w, 0.f);
            v1.x = fmaxf(v1.x, 0.f); v1.y = fmaxf(v1.y, 0.f);
            v1.z = fmaxf(v1.z, 0.f); v1.w = fmaxf(v1.w, 0.f);
        }
        *(float4*)(C + (size_t)row * N + n0 + tx * 8)     = v0;
        *(float4*)(C + (size_t)row * N + n0 + tx * 8 + 4) = v1;
    }
}

// ---------------- fused residual-add + LayerNorm ----------------
__global__ __launch_bounds__(128) void add_ln_kernel(
    const float* __restrict__ x, const float* __restrict__ a,
    const float* __restrict__ g, const float* __restrict__ b,
    float* __restrict__ dst)
{
    int t = blockIdx.x, tid = threadIdx.x;
    float4 v  = ((const float4*)(x + (size_t)t * DMODEL))[tid];
    float4 av = ((const float4*)(a + (size_t)t * DMODEL))[tid];
    v.x += av.x; v.y += av.y; v.z += av.z; v.w += av.w;
    float s  = v.x + v.y + v.z + v.w;
    float sq = v.x * v.x + v.y * v.y + v.z * v.z + v.w * v.w;
#pragma unroll
    for (int o = 16; o > 0; o >>= 1) {
        s  += __shfl_xor_sync(0xffffffffu, s,  o);
        sq += __shfl_xor_sync(0xffffffffu, sq, o);
    }
    __shared__ float ws[4], wq[4];
    int warp = tid >> 5, lane = tid & 31;
    if (lane == 0) { ws[warp] = s; wq[warp] = sq; }
    __syncthreads();
    s  = ws[0] + ws[1] + ws[2] + ws[3];
    sq = wq[0] + wq[1] + wq[2] + wq[3];
    float mean = s * (1.f / 512.f);
    float var  = sq * (1.f / 512.f) - mean * mean;
    float rs = rsqrtf(var + 1e-5f);
    float4 gg  = ((const float4*)g)[tid];
    float4 bb2 = ((const float4*)b)[tid];
    float4 o4;
    o4.x = (v.x - mean) * rs * gg.x + bb2.x;
    o4.y = (v.y - mean) * rs * gg.y + bb2.y;
    o4.z = (v.z - mean) * rs * gg.z + bb2.z;
    o4.w = (v.w - mean) * rs * gg.w + bb2.w;
    ((float4*)(dst + (size_t)t * DMODEL))[tid] = o4;
}

// ---------------- launcher ----------------
extern "C" void kernel_launch(void* const* d_in, const int* in_sizes, int n_in,
                              void* d_out, int out_size)
{
    const int*   src  = (const int*)d_in[0];     // int32 (JAX default x64-off)
    const int*   mask = (const int*)d_in[1];
    const float* emb = (const float*)d_in[2];
    const float* Wq  = (const float*)d_in[3];
    const float* bq  = (const float*)d_in[4];
    const float* Wk  = (const float*)d_in[5];
    const float* bk  = (const float*)d_in[6];
    const float* Wv  = (const float*)d_in[7];
    const float* bv  = (const float*)d_in[8];
    const float* Wo  = (const float*)d_in[9];
    const float* bo  = (const float*)d_in[10];
    const float* W1  = (const float*)d_in[11];
    const float* b1  = (const float*)d_in[12];
    const float* W2  = (const float*)d_in[13];
    const float* b2  = (const float*)d_in[14];
    const float* ln1g = (const float*)d_in[15];
    const float* ln1b = (const float*)d_in[16];
    const float* ln2g = (const float*)d_in[17];
    const float* ln2b = (const float*)d_in[18];
    float* out = (float*)d_out;

    float *h, *q, *k, *v, *att, *proj, *ff;
    cudaGetSymbolAddress((void**)&h,    g_h);
    cudaGetSymbolAddress((void**)&q,    g_q);
    cudaGetSymbolAddress((void**)&k,    g_k);
    cudaGetSymbolAddress((void**)&v,    g_v);
    cudaGetSymbolAddress((void**)&att,  g_att);
    cudaGetSymbolAddress((void**)&proj, g_proj);
    cudaGetSymbolAddress((void**)&ff,   g_ff);

    const size_t flashSmem = 44544 * sizeof(float);  // ~174KB
    cudaFuncSetAttribute(flash_kernel, cudaFuncAttributeMaxDynamicSharedMemorySize,
                         (int)flashSmem);

    embed_kernel<<<T_TOK, 128>>>(src, emb, h);

    for (int l = 0; l < NLAYER; ++l) {
        qkv_kernel<<<256, 128>>>(h,
            Wq + (size_t)l * HDIM * HDIM, Wk + (size_t)l * HDIM * HDIM, Wv + (size_t)l * HDIM * HDIM,
            bq + l * HDIM, bk + l * HDIM, bv + l * HDIM,
            q, k, v);

        flash_kernel<<<dim3(16, NHEAD, 2), 256, flashSmem>>>(q, k, v, mask, att);

        sgemm_bias_kernel<false><<<dim3(4, 32), 256>>>(
            att, Wo + (size_t)l * DMODEL * DMODEL, bo + l * DMODEL, proj,
            T_TOK, DMODEL, DMODEL);

        add_ln_kernel<<<T_TOK, 128>>>(h, proj, ln1g + l * DMODEL, ln1b + l * DMODEL, h);

        sgemm_bias_kernel<true><<<dim3(16, 32), 256>>>(
            h, W1 + (size_t)l * FDIM * DMODEL, b1 + l * FDIM, ff,
            T_TOK, FDIM, DMODEL);

        sgemm_bias_kernel<false><<<dim3(4, 32), 256>>>(
            ff, W2 + (size_t)l * DMODEL * FDIM, b2 + l * DMODEL, proj,
            T_TOK, DMODEL, FDIM);

        add_ln_kernel<<<T_TOK, 128>>>(h, proj, ln2g + l * DMODEL, ln2b + l * DMODEL,
                                      (l == NLAYER - 1) ? out : h);
    }
}

// round 3
// speedup vs baseline: 2.3839x; 2.3839x over previous
#include <cuda_runtime.h>
#include <cstdint>
#include <cstddef>

#define T_TOK 4096
#define DMODEL 512
#define NHEAD 8
#define HDIM 64
#define FDIM 2048
#define NLAYER 6
#define SEQ 2048

// ---------------- scratch (static device globals; no allocation) ----------------
__device__ float g_h[T_TOK * DMODEL];
__device__ float g_q[T_TOK * DMODEL];
__device__ float g_k[T_TOK * DMODEL];
__device__ float g_v[T_TOK * DMODEL];
__device__ float g_att[T_TOK * DMODEL];
__device__ float g_proj[T_TOK * DMODEL];
__device__ float g_ff[T_TOK * FDIM];

// ---------------- tf32 helpers ----------------
__device__ __forceinline__ unsigned f2tf32(float f) {
    unsigned r;
    asm("cvt.rna.tf32.f32 %0, %1;" : "=r"(r) : "f"(f));
    return r;
}

__device__ __forceinline__ void mma_tf32(float d[4], const unsigned a[4], const unsigned b[2]) {
    asm volatile(
        "mma.sync.aligned.m16n8k8.row.col.f32.tf32.tf32.f32 "
        "{%0,%1,%2,%3}, {%4,%5,%6,%7}, {%8,%9}, {%0,%1,%2,%3};"
        : "+f"(d[0]), "+f"(d[1]), "+f"(d[2]), "+f"(d[3])
        : "r"(a[0]), "r"(a[1]), "r"(a[2]), "r"(a[3]), "r"(b[0]), "r"(b[1]));
}

// ---------------- embedding ----------------
__global__ __launch_bounds__(128) void embed_kernel(
    const int* __restrict__ src, const float* __restrict__ emb,
    float* __restrict__ h)
{
    int t = blockIdx.x;
    int tok = src[t];
    const float4* e = (const float4*)(emb + (size_t)tok * DMODEL);
    float4* o = (float4*)(h + (size_t)t * DMODEL);
    const float s = 22.627416997969522f;  // sqrt(512)
    float4 v = e[threadIdx.x];
    v.x *= s; v.y *= s; v.z *= s; v.w *= s;
    o[threadIdx.x] = v;
}

// ---------------- QKV: per-head shared 64x64 projections (fp32, small) ----------------
__global__ __launch_bounds__(128) void qkv_kernel(
    const float* __restrict__ h,
    const float* __restrict__ Wq, const float* __restrict__ Wk, const float* __restrict__ Wv,
    const float* __restrict__ bq, const float* __restrict__ bk, const float* __restrict__ bv,
    float* __restrict__ Q, float* __restrict__ K, float* __restrict__ V)
{
    __shared__ float Ws[3][HDIM * HDIM];
    int tid = threadIdx.x;
    for (int i = tid; i < HDIM * HDIM; i += 128) {
        Ws[0][i] = Wq[i];
        Ws[1][i] = Wk[i];
        Ws[2][i] = Wv[i];
    }
    __syncthreads();

    size_t r = (size_t)blockIdx.x * 128 + tid;
    float4 x[16];
    const float4* xp = (const float4*)(h + r * HDIM);
#pragma unroll
    for (int i = 0; i < 16; i++) x[i] = xp[i];

#pragma unroll
    for (int m = 0; m < 3; m++) {
        const float* W = Ws[m];
        const float* bias = (m == 0) ? bq : ((m == 1) ? bk : bv);
        float* outp = ((m == 0) ? Q : ((m == 1) ? K : V)) + r * HDIM;
        for (int e0 = 0; e0 < HDIM; e0 += 4) {
            float acc[4] = {0.f, 0.f, 0.f, 0.f};
#pragma unroll
            for (int c = 0; c < 4; c++) {
                const float4* w4 = (const float4*)(W + (e0 + c) * HDIM);
#pragma unroll
                for (int i = 0; i < 16; i++) {
                    float4 w = w4[i];
                    acc[c] += x[i].x * w.x + x[i].y * w.y + x[i].z * w.z + x[i].w * w.w;
                }
            }
            float4 ov;
            ov.x = acc[0] + bias[e0 + 0];
            ov.y = acc[1] + bias[e0 + 1];
            ov.z = acc[2] + bias[e0 + 2];
            ov.w = acc[3] + bias[e0 + 3];
            *(float4*)(outp + e0) = ov;
        }
    }
}

// ---------------- flash attention (tf32 mma, online softmax) ----------------
// block: 256 threads (8 warps, 2x4), 128 q-rows x 128 kv tiles, HD=64
#define QK_LD 68   // smem stride for Q/K/V tiles ((4g+k)%32 conflict-free)
#define P_LD 132   // smem stride for P tile

__global__ __launch_bounds__(256) void flash_kernel(
    const float* __restrict__ Qg, const float* __restrict__ Kg,
    const float* __restrict__ Vg, const int* __restrict__ mask,
    float* __restrict__ Og)
{
    extern __shared__ float sm[];
    float* Q_s  = sm;                     // [128][68]
    float* K_s  = Q_s + 128 * QK_LD;      // [128][68]
    float* V_s  = K_s + 128 * QK_LD;      // [128][68]
    float* P_s  = V_s + 128 * QK_LD;      // [128][132]
    float* mrow = P_s + 128 * P_LD;       // [128]
    float* crow = mrow + 128;             // [128]
    float* lrow = crow + 128;             // [128]
    float* red  = lrow + 128;             // [128][4]
    float* mkv  = red + 512;              // [128]

    int tid = threadIdx.x;
    int warp = tid >> 5, lane = tid & 31;
    int g = lane >> 2, l4 = lane & 3;
    int wm = warp >> 2, wn = warp & 3;    // 2 x 4 warp grid

    int qt = blockIdx.x, hh = blockIdx.y, n = blockIdx.z;
    int q0 = qt * 128;
    size_t baseQ = ((size_t)(n * SEQ + q0)) * DMODEL + hh * HDIM;

    // load Q tile (tf32-rounded)
#pragma unroll
    for (int it = 0; it < 8; ++it) {
        int idx = tid + it * 256;
        int row = idx >> 4, q4 = idx & 15;
        float4 v = *(const float4*)(Qg + baseQ + (size_t)row * DMODEL + q4 * 4);
        float* d = &Q_s[row * QK_LD + q4 * 4];
        d[0] = __uint_as_float(f2tf32(v.x));
        d[1] = __uint_as_float(f2tf32(v.y));
        d[2] = __uint_as_float(f2tf32(v.z));
        d[3] = __uint_as_float(f2tf32(v.w));
    }
    if (tid < 128) { mrow[tid] = -3.0e38f; lrow[tid] = 0.f; }

    float o[4][2][4];
#pragma unroll
    for (int mi = 0; mi < 4; mi++)
#pragma unroll
        for (int ni = 0; ni < 2; ni++)
#pragma unroll
            for (int j = 0; j < 4; j++) o[mi][ni][j] = 0.f;
    __syncthreads();

    const float INV    = 0.04419417382415922f;   // 1/sqrt(512)
    const float MASKED = -1e10f * 0.04419417382415922f;

    for (int kt = 0; kt < 16; ++kt) {
        int k0g = kt * 128;
        size_t baseK = ((size_t)(n * SEQ + k0g)) * DMODEL + hh * HDIM;
#pragma unroll
        for (int it = 0; it < 8; ++it) {
            int idx = tid + it * 256;
            int row = idx >> 4, q4 = idx & 15;
            float4 kv = *(const float4*)(Kg + baseK + (size_t)row * DMODEL + q4 * 4);
            float* dk = &K_s[row * QK_LD + q4 * 4];
            dk[0] = __uint_as_float(f2tf32(kv.x));
            dk[1] = __uint_as_float(f2tf32(kv.y));
            dk[2] = __uint_as_float(f2tf32(kv.z));
            dk[3] = __uint_as_float(f2tf32(kv.w));
            float4 vv = *(const float4*)(Vg + baseK + (size_t)row * DMODEL + q4 * 4);
            float* dv = &V_s[row * QK_LD + q4 * 4];
            dv[0] = __uint_as_float(f2tf32(vv.x));
            dv[1] = __uint_as_float(f2tf32(vv.y));
            dv[2] = __uint_as_float(f2tf32(vv.z));
            dv[3] = __uint_as_float(f2tf32(vv.w));
        }
        if (tid < 128) mkv[tid] = (float)mask[n * SEQ + k0g + tid];
        __syncthreads();

        // ---- S = Q @ K^T via tf32 mma; warp tile 64x32 ----
        float s[4][4][4];
#pragma unroll
        for (int mi = 0; mi < 4; mi++)
#pragma unroll
            for (int ni = 0; ni < 4; ni++)
#pragma unroll
                for (int j = 0; j < 4; j++) s[mi][ni][j] = 0.f;

#pragma unroll
        for (int ks = 0; ks < 8; ++ks) {
            int k = ks * 8;
            unsigned a[4][4], b[4][2];
#pragma unroll
            for (int mi = 0; mi < 4; mi++) {
                int rb = wm * 64 + mi * 16;
                a[mi][0] = __float_as_uint(Q_s[(rb + g) * QK_LD + k + l4]);
                a[mi][1] = __float_as_uint(Q_s[(rb + g + 8) * QK_LD + k + l4]);
                a[mi][2] = __float_as_uint(Q_s[(rb + g) * QK_LD + k + l4 + 4]);
                a[mi][3] = __float_as_uint(Q_s[(rb + g + 8) * QK_LD + k + l4 + 4]);
            }
#pragma unroll
            for (int ni = 0; ni < 4; ni++) {
                int nb = wn * 32 + ni * 8;
                b[ni][0] = __float_as_uint(K_s[(nb + g) * QK_LD + k + l4]);
                b[ni][1] = __float_as_uint(K_s[(nb + g) * QK_LD + k + l4 + 4]);
            }
#pragma unroll
            for (int mi = 0; mi < 4; mi++)
#pragma unroll
                for (int ni = 0; ni < 4; ni++)
                    mma_tf32(s[mi][ni], a[mi], b[ni]);
        }

        // ---- mask + scale, per-thread row maxes ----
        float m0v[4], m1v[4];
#pragma unroll
        for (int mi = 0; mi < 4; mi++) { m0v[mi] = -3.0e38f; m1v[mi] = -3.0e38f; }
#pragma unroll
        for (int ni = 0; ni < 4; ni++) {
            int c = wn * 32 + ni * 8 + l4 * 2;
            float mk0 = mkv[c], mk1 = mkv[c + 1];
#pragma unroll
            for (int mi = 0; mi < 4; mi++) {
                s[mi][ni][0] = (mk0 == 0.f) ? MASKED : s[mi][ni][0] * INV;
                s[mi][ni][1] = (mk1 == 0.f) ? MASKED : s[mi][ni][1] * INV;
                s[mi][ni][2] = (mk0 == 0.f) ? MASKED : s[mi][ni][2] * INV;
                s[mi][ni][3] = (mk1 == 0.f) ? MASKED : s[mi][ni][3] * INV;
                m0v[mi] = fmaxf(m0v[mi], fmaxf(s[mi][ni][0], s[mi][ni][1]));
                m1v[mi] = fmaxf(m1v[mi], fmaxf(s[mi][ni][2], s[mi][ni][3]));
            }
        }
        // reduce over quad (lanes sharing the same row)
#pragma unroll
        for (int mi = 0; mi < 4; mi++) {
            m0v[mi] = fmaxf(m0v[mi], __shfl_xor_sync(0xffffffffu, m0v[mi], 1));
            m0v[mi] = fmaxf(m0v[mi], __shfl_xor_sync(0xffffffffu, m0v[mi], 2));
            m1v[mi] = fmaxf(m1v[mi], __shfl_xor_sync(0xffffffffu, m1v[mi], 1));
            m1v[mi] = fmaxf(m1v[mi], __shfl_xor_sync(0xffffffffu, m1v[mi], 2));
            if (l4 == 0) {
                int r0 = wm * 64 + mi * 16 + g;
                red[r0 * 4 + wn] = m0v[mi];
                red[(r0 + 8) * 4 + wn] = m1v[mi];
            }
        }
        __syncthreads();   // B: maxes visible
        if (tid < 128) {
            float mo = mrow[tid];
            float mx = fmaxf(fmaxf(red[tid * 4 + 0], red[tid * 4 + 1]),
                             fmaxf(red[tid * 4 + 2], red[tid * 4 + 3]));
            mx = fmaxf(mo, mx);
            crow[tid] = __expf(mo - mx);
            mrow[tid] = mx;
        }
        __syncthreads();   // C: mrow/crow valid

        // ---- P = exp(s - mrow) -> smem (tf32), partial row sums ----
#pragma unroll
        for (int mi = 0; mi < 4; mi++) {
            int r0 = wm * 64 + mi * 16 + g;
            int r1 = r0 + 8;
            float mr0 = mrow[r0], mr1 = mrow[r1];
            float ps0 = 0.f, ps1 = 0.f;
#pragma unroll
            for (int ni = 0; ni < 4; ni++) {
                int c = wn * 32 + ni * 8 + l4 * 2;
                float p00 = __expf(s[mi][ni][0] - mr0);
                float p01 = __expf(s[mi][ni][1] - mr0);
                float p10 = __expf(s[mi][ni][2] - mr1);
                float p11 = __expf(s[mi][ni][3] - mr1);
                ps0 += p00 + p01;
                ps1 += p10 + p11;
                P_s[r0 * P_LD + c]     = __uint_as_float(f2tf32(p00));
                P_s[r0 * P_LD + c + 1] = __uint_as_float(f2tf32(p01));
                P_s[r1 * P_LD + c]     = __uint_as_float(f2tf32(p10));
                P_s[r1 * P_LD + c + 1] = __uint_as_float(f2tf32(p11));
            }
            ps0 += __shfl_xor_sync(0xffffffffu, ps0, 1);
            ps0 += __shfl_xor_sync(0xffffffffu, ps0, 2);
            ps1 += __shfl_xor_sync(0xffffffffu, ps1, 1);
            ps1 += __shfl_xor_sync(0xffffffffu, ps1, 2);
            if (l4 == 0) {
                red[r0 * 4 + wn] = ps0;
                red[r1 * 4 + wn] = ps1;
            }
            // rescale O accumulators for these rows
            float c0 = crow[r0], c1 = crow[r1];
#pragma unroll
            for (int ni = 0; ni < 2; ni++) {
                o[mi][ni][0] *= c0; o[mi][ni][1] *= c0;
                o[mi][ni][2] *= c1; o[mi][ni][3] *= c1;
            }
        }
        __syncthreads();   // D: P_s + sums visible
        if (tid < 128) {
            float s2 = red[tid * 4 + 0] + red[tid * 4 + 1] + red[tid * 4 + 2] + red[tid * 4 + 3];
            lrow[tid] = lrow[tid] * crow[tid] + s2;
        }

        // ---- O += P @ V via tf32 mma; warp tile 64x16 over d ----
#pragma unroll
        for (int ks = 0; ks < 16; ++ks) {
            int k = ks * 8;
            unsigned a[4][4], b[2][2];
#pragma unroll
            for (int mi = 0; mi < 4; mi++) {
                int rb = wm * 64 + mi * 16;
                a[mi][0] = __float_as_uint(P_s[(rb + g) * P_LD + k + l4]);
                a[mi][1] = __float_as_uint(P_s[(rb + g + 8) * P_LD + k + l4]);
                a[mi][2] = __float_as_uint(P_s[(rb + g) * P_LD + k + l4 + 4]);
                a[mi][3] = __float_as_uint(P_s[(rb + g + 8) * P_LD + k + l4 + 4]);
            }
#pragma unroll
            for (int ni = 0; ni < 2; ni++) {
                int cb = wn * 16 + ni * 8;
                b[ni][0] = __float_as_uint(V_s[(k + l4) * QK_LD + cb + g]);
                b[ni][1] = __float_as_uint(V_s[(k + l4 + 4) * QK_LD + cb + g]);
            }
#pragma unroll
            for (int mi = 0; mi < 4; mi++)
#pragma unroll
                for (int ni = 0; ni < 2; ni++)
                    mma_tf32(o[mi][ni], a[mi], b[ni]);
        }
        __syncthreads();   // E: done with K_s/V_s/P_s this iter
    }

    // epilogue: divide by lrow, write out
#pragma unroll
    for (int mi = 0; mi < 4; mi++) {
        int r0 = wm * 64 + mi * 16 + g;
        int r1 = r0 + 8;
        float li0 = 1.f / lrow[r0];
        float li1 = 1.f / lrow[r1];
#pragma unroll
        for (int ni = 0; ni < 2; ni++) {
            int c = wn * 16 + ni * 8 + l4 * 2;
            float2 v0 = {o[mi][ni][0] * li0, o[mi][ni][1] * li0};
            float2 v1 = {o[mi][ni][2] * li1, o[mi][ni][3] * li1};
            *(float2*)(Og + baseQ + (size_t)r0 * DMODEL + c) = v0;
            *(float2*)(Og + baseQ + (size_t)r1 * DMODEL + c) = v1;
        }
    }
}

// ---------------- tf32 SGEMM: C[M,N] = A[M,K] @ B[N,K]^T + bias (opt ReLU) ----------------
#define G_LD 36   // smem stride for 32-wide k tiles

template <bool RELU>
__global__ __launch_bounds__(256) void sgemm_tf32_kernel(
    const float* __restrict__ A, const float* __restrict__ B,
    const float* __restrict__ bias, float* __restrict__ C,
    int M, int N, int K)
{
    __shared__ float A_s[128 * G_LD];
    __shared__ float B_s[128 * G_LD];
    int tid = threadIdx.x;
    int warp = tid >> 5, lane = tid & 31;
    int g = lane >> 2, l4 = lane & 3;
    int wm = warp >> 2, wn = warp & 3;
    int n0 = blockIdx.x * 128, m0 = blockIdx.y * 128;

    float acc[4][4][4];
#pragma unroll
    for (int mi = 0; mi < 4; mi++)
#pragma unroll
        for (int ni = 0; ni < 4; ni++)
#pragma unroll
            for (int j = 0; j < 4; j++) acc[mi][ni][j] = 0.f;

    for (int kb = 0; kb < K; kb += 32) {
#pragma unroll
        for (int it = 0; it < 4; ++it) {
            int idx = tid + it * 256;
            int row = idx >> 3, kq = idx & 7;
            float4 av = *(const float4*)(A + (size_t)(m0 + row) * K + kb + kq * 4);
            float* da = &A_s[row * G_LD + kq * 4];
            da[0] = __uint_as_float(f2tf32(av.x));
            da[1] = __uint_as_float(f2tf32(av.y));
            da[2] = __uint_as_float(f2tf32(av.z));
            da[3] = __uint_as_float(f2tf32(av.w));
            float4 bv = *(const float4*)(B + (size_t)(n0 + row) * K + kb + kq * 4);
            float* db = &B_s[row * G_LD + kq * 4];
            db[0] = __uint_as_float(f2tf32(bv.x));
            db[1] = __uint_as_float(f2tf32(bv.y));
            db[2] = __uint_as_float(f2tf32(bv.z));
            db[3] = __uint_as_float(f2tf32(bv.w));
        }
        __syncthreads();

#pragma unroll
        for (int ks = 0; ks < 4; ++ks) {
            int k = ks * 8;
            unsigned a[4][4], b[4][2];
#pragma unroll
            for (int mi = 0; mi < 4; mi++) {
                int rb = wm * 64 + mi * 16;
                a[mi][0] = __float_as_uint(A_s[(rb + g) * G_LD + k + l4]);
                a[mi][1] = __float_as_uint(A_s[(rb + g + 8) * G_LD + k + l4]);
                a[mi][2] = __float_as_uint(A_s[(rb + g) * G_LD + k + l4 + 4]);
                a[mi][3] = __float_as_uint(A_s[(rb + g + 8) * G_LD + k + l4 + 4]);
            }
#pragma unroll
            for (int ni = 0; ni < 4; ni++) {
                int nb = wn * 32 + ni * 8;
                b[ni][0] = __float_as_uint(B_s[(nb + g) * G_LD + k + l4]);
                b[ni][1] = __float_as_uint(B_s[(nb + g) * G_LD + k + l4 + 4]);
            }
#pragma unroll
            for (int mi = 0; mi < 4; mi++)
#pragma unroll
                for (int ni = 0; ni < 4; ni++)
                    mma_tf32(acc[mi][ni], a[mi], b[ni]);
        }
        __syncthreads();
    }

    // epilogue: bias (+ReLU), float2 stores
#pragma unroll
    for (int ni = 0; ni < 4; ni++) {
        int c = n0 + wn * 32 + ni * 8 + l4 * 2;
        float b0 = bias[c], b1 = bias[c + 1];
#pragma unroll
        for (int mi = 0; mi < 4; mi++) {
            int r0 = m0 + wm * 64 + mi * 16 + g;
            int r1 = r0 + 8;
            float2 v0 = {acc[mi][ni][0] + b0, acc[mi][ni][1] + b1};
            float2 v1 = {acc[mi][ni][2] + b0, acc[mi][ni][3] + b1};
            if (RELU) {
                v0.x = fmaxf(v0.x, 0.f); v0.y = fmaxf(v0.y, 0.f);
                v1.x = fmaxf(v1.x, 0.f); v1.y = fmaxf(v1.y, 0.f);
            }
            *(float2*)(C + (size_t)r0 * N + c) = v0;
            *(float2*)(C + (size_t)r1 * N + c) = v1;
        }
    }
}

// ---------------- fused residual-add + LayerNorm ----------------
__global__ __launch_bounds__(128) void add_ln_kernel(
    const float* __restrict__ x, const float* __restrict__ a,
    const float* __restrict__ g, const float* __restrict__ b,
    float* __restrict__ dst)
{
    int t = blockIdx.x, tid = threadIdx.x;
    float4 v  = ((const float4*)(x + (size_t)t * DMODEL))[tid];
    float4 av = ((const float4*)(a + (size_t)t * DMODEL))[tid];
    v.x += av.x; v.y += av.y; v.z += av.z; v.w += av.w;
    float s  = v.x + v.y + v.z + v.w;
    float sq = v.x * v.x + v.y * v.y + v.z * v.z + v.w * v.w;
#pragma unroll
    for (int o = 16; o > 0; o >>= 1) {
        s  += __shfl_xor_sync(0xffffffffu, s,  o);
        sq += __shfl_xor_sync(0xffffffffu, sq, o);
    }
    __shared__ float ws[4], wq[4];
    int warp = tid >> 5, lane = tid & 31;
    if (lane == 0) { ws[warp] = s; wq[warp] = sq; }
    __syncthreads();
    s  = ws[0] + ws[1] + ws[2] + ws[3];
    sq = wq[0] + wq[1] + wq[2] + wq[3];
    float mean = s * (1.f / 512.f);
    float var  = sq * (1.f / 512.f) - mean * mean;
    float rs = rsqrtf(var + 1e-5f);
    float4 gg  = ((const float4*)g)[tid];
    float4 bb2 = ((const float4*)b)[tid];
    float4 o4;
    o4.x = (v.x - mean) * rs * gg.x + bb2.x;
    o4.y = (v.y - mean) * rs * gg.y + bb2.y;
    o4.z = (v.z - mean) * rs * gg.z + bb2.z;
    o4.w = (v.w - mean) * rs * gg.w + bb2.w;
    ((float4*)(dst + (size_t)t * DMODEL))[tid] = o4;
}

// ---------------- launcher ----------------
extern "C" void kernel_launch(void* const* d_in, const int* in_sizes, int n_in,
                              void* d_out, int out_size)
{
    const int*   src  = (const int*)d_in[0];     // int32 (JAX default x64-off)
    const int*   mask = (const int*)d_in[1];
    const float* emb = (const float*)d_in[2];
    const float* Wq  = (const float*)d_in[3];
    const float* bq  = (const float*)d_in[4];
    const float* Wk  = (const float*)d_in[5];
    const float* bk  = (const float*)d_in[6];
    const float* Wv  = (const float*)d_in[7];
    const float* bv  = (const float*)d_in[8];
    const float* Wo  = (const float*)d_in[9];
    const float* bo  = (const float*)d_in[10];
    const float* W1  = (const float*)d_in[11];
    const float* b1  = (const float*)d_in[12];
    const float* W2  = (const float*)d_in[13];
    const float* b2  = (const float*)d_in[14];
    const float* ln1g = (const float*)d_in[15];
    const float* ln1b = (const float*)d_in[16];
    const float* ln2g = (const float*)d_in[17];
    const float* ln2b = (const float*)d_in[18];
    float* out = (float*)d_out;

    float *h, *q, *k, *v, *att, *proj, *ff;
    cudaGetSymbolAddress((void**)&h,    g_h);
    cudaGetSymbolAddress((void**)&q,    g_q);
    cudaGetSymbolAddress((void**)&k,    g_k);
    cudaGetSymbolAddress((void**)&v,    g_v);
    cudaGetSymbolAddress((void**)&att,  g_att);
    cudaGetSymbolAddress((void**)&proj, g_proj);
    cudaGetSymbolAddress((void**)&ff,   g_ff);

    // flash smem: 3*128*68 + 128*132 + 3*128 + 512 + 128 floats
    const size_t flashSmem = (size_t)(3 * 128 * QK_LD + 128 * P_LD + 3 * 128 + 512 + 128)
                             * sizeof(float);
    cudaFuncSetAttribute(flash_kernel, cudaFuncAttributeMaxDynamicSharedMemorySize,
                         (int)flashSmem);

    embed_kernel<<<T_TOK, 128>>>(src, emb, h);

    for (int l = 0; l < NLAYER; ++l) {
        qkv_kernel<<<256, 128>>>(h,
            Wq + (size_t)l * HDIM * HDIM, Wk + (size_t)l * HDIM * HDIM, Wv + (size_t)l * HDIM * HDIM,
            bq + l * HDIM, bk + l * HDIM, bv + l * HDIM,
            q, k, v);

        flash_kernel<<<dim3(16, NHEAD, 2), 256, flashSmem>>>(q, k, v, mask, att);

        sgemm_tf32_kernel<false><<<dim3(4, 32), 256>>>(
            att, Wo + (size_t)l * DMODEL * DMODEL, bo + l * DMODEL, proj,
            T_TOK, DMODEL, DMODEL);

        add_ln_kernel<<<T_TOK, 128>>>(h, proj, ln1g + l * DMODEL, ln1b + l * DMODEL, h);

        sgemm_tf32_kernel<true><<<dim3(16, 32), 256>>>(
            h, W1 + (size_t)l * FDIM * DMODEL, b1 + l * FDIM, ff,
            T_TOK, FDIM, DMODEL);

        sgemm_tf32_kernel<false><<<dim3(4, 32), 256>>>(
            ff, W2 + (size_t)l * DMODEL * FDIM, b2 + l * DMODEL, proj,
            T_TOK, DMODEL, FDIM);

        add_ln_kernel<<<T_TOK, 128>>>(h, proj, ln2g + l * DMODEL, ln2b + l * DMODEL,
                                      (l == NLAYER - 1) ? out : h);
    }
}

// round 4
// speedup vs baseline: 2.8753x; 1.2061x over previous
#include <cuda_runtime.h>
#include <cstdint>
#include <cstddef>

#define T_TOK 4096
#define DMODEL 512
#define NHEAD 8
#define HDIM 64
#define FDIM 2048
#define NLAYER 6
#define SEQ 2048

// ---------------- scratch (static device globals; no allocation) ----------------
__device__ float g_h[T_TOK * DMODEL];
__device__ float g_htf[T_TOK * DMODEL];          // tf32-rounded copy of h for W1
__device__ float g_q[T_TOK * DMODEL];
__device__ float g_k[T_TOK * DMODEL];
__device__ float g_v[T_TOK * DMODEL];
__device__ float g_att[T_TOK * DMODEL];
__device__ float g_proj[T_TOK * DMODEL];
__device__ float g_ff[T_TOK * FDIM];
__device__ float g_wo_t[NLAYER * DMODEL * DMODEL];   // tf32-rounded weights
__device__ float g_w1_t[NLAYER * FDIM * DMODEL];
__device__ float g_w2_t[NLAYER * DMODEL * FDIM];

// ---------------- tf32 / cp.async helpers ----------------
__device__ __forceinline__ unsigned f2tf32(float f) {
    unsigned r;
    asm("cvt.rna.tf32.f32 %0, %1;" : "=r"(r) : "f"(f));
    return r;
}
__device__ __forceinline__ float f2tf32f(float f) { return __uint_as_float(f2tf32(f)); }

__device__ __forceinline__ void mma_tf32(float d[4], const unsigned a[4], const unsigned b[2]) {
    asm volatile(
        "mma.sync.aligned.m16n8k8.row.col.f32.tf32.tf32.f32 "
        "{%0,%1,%2,%3}, {%4,%5,%6,%7}, {%8,%9}, {%0,%1,%2,%3};"
        : "+f"(d[0]), "+f"(d[1]), "+f"(d[2]), "+f"(d[3])
        : "r"(a[0]), "r"(a[1]), "r"(a[2]), "r"(a[3]), "r"(b[0]), "r"(b[1]));
}

__device__ __forceinline__ void cp_async16(uint32_t dst, const void* src) {
    asm volatile("cp.async.ca.shared.global [%0], [%1], 16;" :: "r"(dst), "l"(src));
}
__device__ __forceinline__ void cp_commit() {
    asm volatile("cp.async.commit_group;");
}
template <int N>
__device__ __forceinline__ void cp_wait() {
    asm volatile("cp.async.wait_group %0;" :: "n"(N));
}

// ---------------- weight rounding (fp32 -> tf32 bits) ----------------
__global__ __launch_bounds__(256) void round_tf32_kernel(
    const float4* __restrict__ x, float4* __restrict__ y, int n4)
{
    int i = blockIdx.x * 256 + threadIdx.x;
    if (i < n4) {
        float4 v = x[i];
        v.x = f2tf32f(v.x); v.y = f2tf32f(v.y);
        v.z = f2tf32f(v.z); v.w = f2tf32f(v.w);
        y[i] = v;
    }
}

// ---------------- embedding ----------------
__global__ __launch_bounds__(128) void embed_kernel(
    const int* __restrict__ src, const float* __restrict__ emb,
    float* __restrict__ h)
{
    int t = blockIdx.x;
    int tok = src[t];
    const float4* e = (const float4*)(emb + (size_t)tok * DMODEL);
    float4* o = (float4*)(h + (size_t)t * DMODEL);
    const float s = 22.627416997969522f;  // sqrt(512)
    float4 v = e[threadIdx.x];
    v.x *= s; v.y *= s; v.z *= s; v.w *= s;
    o[threadIdx.x] = v;
}

// ---------------- QKV: per-head shared 64x64 projections (fp32 math, tf32-rounded out) ----------------
__global__ __launch_bounds__(128) void qkv_kernel(
    const float* __restrict__ h,
    const float* __restrict__ Wq, const float* __restrict__ Wk, const float* __restrict__ Wv,
    const float* __restrict__ bq, const float* __restrict__ bk, const float* __restrict__ bv,
    float* __restrict__ Q, float* __restrict__ K, float* __restrict__ V)
{
    __shared__ float Ws[3][HDIM * HDIM];
    int tid = threadIdx.x;
    for (int i = tid; i < HDIM * HDIM; i += 128) {
        Ws[0][i] = Wq[i];
        Ws[1][i] = Wk[i];
        Ws[2][i] = Wv[i];
    }
    __syncthreads();

    size_t r = (size_t)blockIdx.x * 128 + tid;
    float4 x[16];
    const float4* xp = (const float4*)(h + r * HDIM);
#pragma unroll
    for (int i = 0; i < 16; i++) x[i] = xp[i];

#pragma unroll
    for (int m = 0; m < 3; m++) {
        const float* W = Ws[m];
        const float* bias = (m == 0) ? bq : ((m == 1) ? bk : bv);
        float* outp = ((m == 0) ? Q : ((m == 1) ? K : V)) + r * HDIM;
        for (int e0 = 0; e0 < HDIM; e0 += 4) {
            float acc[4] = {0.f, 0.f, 0.f, 0.f};
#pragma unroll
            for (int c = 0; c < 4; c++) {
                const float4* w4 = (const float4*)(W + (e0 + c) * HDIM);
#pragma unroll
                for (int i = 0; i < 16; i++) {
                    float4 w = w4[i];
                    acc[c] += x[i].x * w.x + x[i].y * w.y + x[i].z * w.z + x[i].w * w.w;
                }
            }
            float4 ov;
            ov.x = f2tf32f(acc[0] + bias[e0 + 0]);
            ov.y = f2tf32f(acc[1] + bias[e0 + 1]);
            ov.z = f2tf32f(acc[2] + bias[e0 + 2]);
            ov.w = f2tf32f(acc[3] + bias[e0 + 3]);
            *(float4*)(outp + e0) = ov;
        }
    }
}

// ---------------- flash attention (tf32 mma, online softmax) ----------------
#define QK_LD 68
#define P_LD 132

__global__ __launch_bounds__(256) void flash_kernel(
    const float* __restrict__ Qg, const float* __restrict__ Kg,
    const float* __restrict__ Vg, const int* __restrict__ mask,
    float* __restrict__ Og)
{
    extern __shared__ float sm[];
    float* Q_s  = sm;                     // [128][68]
    float* K_s  = Q_s + 128 * QK_LD;      // [128][68]
    float* V_s  = K_s + 128 * QK_LD;      // [128][68]
    float* P_s  = V_s + 128 * QK_LD;      // [128][132]
    float* mrow = P_s + 128 * P_LD;
    float* crow = mrow + 128;
    float* lrow = crow + 128;
    float* red  = lrow + 128;             // [128][4]
    float* mkv  = red + 512;              // [128]

    int tid = threadIdx.x;
    int warp = tid >> 5, lane = tid & 31;
    int g = lane >> 2, l4 = lane & 3;
    int wm = warp >> 2, wn = warp & 3;

    int qt = blockIdx.x, hh = blockIdx.y, n = blockIdx.z;
    int q0 = qt * 128;
    size_t baseQ = ((size_t)(n * SEQ + q0)) * DMODEL + hh * HDIM;

    // load Q tile (inputs pre-rounded to tf32 by qkv)
#pragma unroll
    for (int it = 0; it < 8; ++it) {
        int idx = tid + it * 256;
        int row = idx >> 4, q4 = idx & 15;
        float4 v = *(const float4*)(Qg + baseQ + (size_t)row * DMODEL + q4 * 4);
        *(float4*)&Q_s[row * QK_LD + q4 * 4] = v;
    }
    if (tid < 128) { mrow[tid] = -3.0e38f; lrow[tid] = 0.f; }

    float o[4][2][4];
#pragma unroll
    for (int mi = 0; mi < 4; mi++)
#pragma unroll
        for (int ni = 0; ni < 2; ni++)
#pragma unroll
            for (int j = 0; j < 4; j++) o[mi][ni][j] = 0.f;
    __syncthreads();

    const float INV    = 0.04419417382415922f;   // 1/sqrt(512)
    const float MASKED = -1e10f * 0.04419417382415922f;

    for (int kt = 0; kt < 16; ++kt) {
        int k0g = kt * 128;
        size_t baseK = ((size_t)(n * SEQ + k0g)) * DMODEL + hh * HDIM;
#pragma unroll
        for (int it = 0; it < 8; ++it) {
            int idx = tid + it * 256;
            int row = idx >> 4, q4 = idx & 15;
            float4 kv = *(const float4*)(Kg + baseK + (size_t)row * DMODEL + q4 * 4);
            *(float4*)&K_s[row * QK_LD + q4 * 4] = kv;
            float4 vv = *(const float4*)(Vg + baseK + (size_t)row * DMODEL + q4 * 4);
            *(float4*)&V_s[row * QK_LD + q4 * 4] = vv;
        }
        if (tid < 128) mkv[tid] = (float)mask[n * SEQ + k0g + tid];
        __syncthreads();

        // ---- S = Q @ K^T ----
        float s[4][4][4];
#pragma unroll
        for (int mi = 0; mi < 4; mi++)
#pragma unroll
            for (int ni = 0; ni < 4; ni++)
#pragma unroll
                for (int j = 0; j < 4; j++) s[mi][ni][j] = 0.f;

#pragma unroll
        for (int ks = 0; ks < 8; ++ks) {
            int k = ks * 8;
            unsigned a[4][4], b[4][2];
#pragma unroll
            for (int mi = 0; mi < 4; mi++) {
                int rb = wm * 64 + mi * 16;
                a[mi][0] = __float_as_uint(Q_s[(rb + g) * QK_LD + k + l4]);
                a[mi][1] = __float_as_uint(Q_s[(rb + g + 8) * QK_LD + k + l4]);
                a[mi][2] = __float_as_uint(Q_s[(rb + g) * QK_LD + k + l4 + 4]);
                a[mi][3] = __float_as_uint(Q_s[(rb + g + 8) * QK_LD + k + l4 + 4]);
            }
#pragma unroll
            for (int ni = 0; ni < 4; ni++) {
                int nb = wn * 32 + ni * 8;
                b[ni][0] = __float_as_uint(K_s[(nb + g) * QK_LD + k + l4]);
                b[ni][1] = __float_as_uint(K_s[(nb + g) * QK_LD + k + l4 + 4]);
            }
#pragma unroll
            for (int mi = 0; mi < 4; mi++)
#pragma unroll
                for (int ni = 0; ni < 4; ni++)
                    mma_tf32(s[mi][ni], a[mi], b[ni]);
        }

        // ---- mask + scale, per-thread row maxes ----
        float m0v[4], m1v[4];
#pragma unroll
        for (int mi = 0; mi < 4; mi++) { m0v[mi] = -3.0e38f; m1v[mi] = -3.0e38f; }
#pragma unroll
        for (int ni = 0; ni < 4; ni++) {
            int c = wn * 32 + ni * 8 + l4 * 2;
            float mk0 = mkv[c], mk1 = mkv[c + 1];
#pragma unroll
            for (int mi = 0; mi < 4; mi++) {
                s[mi][ni][0] = (mk0 == 0.f) ? MASKED : s[mi][ni][0] * INV;
                s[mi][ni][1] = (mk1 == 0.f) ? MASKED : s[mi][ni][1] * INV;
                s[mi][ni][2] = (mk0 == 0.f) ? MASKED : s[mi][ni][2] * INV;
                s[mi][ni][3] = (mk1 == 0.f) ? MASKED : s[mi][ni][3] * INV;
                m0v[mi] = fmaxf(m0v[mi], fmaxf(s[mi][ni][0], s[mi][ni][1]));
                m1v[mi] = fmaxf(m1v[mi], fmaxf(s[mi][ni][2], s[mi][ni][3]));
            }
        }
#pragma unroll
        for (int mi = 0; mi < 4; mi++) {
            m0v[mi] = fmaxf(m0v[mi], __shfl_xor_sync(0xffffffffu, m0v[mi], 1));
            m0v[mi] = fmaxf(m0v[mi], __shfl_xor_sync(0xffffffffu, m0v[mi], 2));
            m1v[mi] = fmaxf(m1v[mi], __shfl_xor_sync(0xffffffffu, m1v[mi], 1));
            m1v[mi] = fmaxf(m1v[mi], __shfl_xor_sync(0xffffffffu, m1v[mi], 2));
            if (l4 == 0) {
                int r0 = wm * 64 + mi * 16 + g;
                red[r0 * 4 + wn] = m0v[mi];
                red[(r0 + 8) * 4 + wn] = m1v[mi];
            }
        }
        __syncthreads();
        if (tid < 128) {
            float mo = mrow[tid];
            float mx = fmaxf(fmaxf(red[tid * 4 + 0], red[tid * 4 + 1]),
                             fmaxf(red[tid * 4 + 2], red[tid * 4 + 3]));
            mx = fmaxf(mo, mx);
            crow[tid] = __expf(mo - mx);
            mrow[tid] = mx;
        }
        __syncthreads();

        // ---- P = exp(s - mrow) -> smem (tf32), partial row sums ----
#pragma unroll
        for (int mi = 0; mi < 4; mi++) {
            int r0 = wm * 64 + mi * 16 + g;
            int r1 = r0 + 8;
            float mr0 = mrow[r0], mr1 = mrow[r1];
            float ps0 = 0.f, ps1 = 0.f;
#pragma unroll
            for (int ni = 0; ni < 4; ni++) {
                int c = wn * 32 + ni * 8 + l4 * 2;
                float p00 = __expf(s[mi][ni][0] - mr0);
                float p01 = __expf(s[mi][ni][1] - mr0);
                float p10 = __expf(s[mi][ni][2] - mr1);
                float p11 = __expf(s[mi][ni][3] - mr1);
                ps0 += p00 + p01;
                ps1 += p10 + p11;
                P_s[r0 * P_LD + c]     = f2tf32f(p00);
                P_s[r0 * P_LD + c + 1] = f2tf32f(p01);
                P_s[r1 * P_LD + c]     = f2tf32f(p10);
                P_s[r1 * P_LD + c + 1] = f2tf32f(p11);
            }
            ps0 += __shfl_xor_sync(0xffffffffu, ps0, 1);
            ps0 += __shfl_xor_sync(0xffffffffu, ps0, 2);
            ps1 += __shfl_xor_sync(0xffffffffu, ps1, 1);
            ps1 += __shfl_xor_sync(0xffffffffu, ps1, 2);
            if (l4 == 0) {
                red[r0 * 4 + wn] = ps0;
                red[r1 * 4 + wn] = ps1;
            }
            float c0 = crow[r0], c1 = crow[r1];
#pragma unroll
            for (int ni = 0; ni < 2; ni++) {
                o[mi][ni][0] *= c0; o[mi][ni][1] *= c0;
                o[mi][ni][2] *= c1; o[mi][ni][3] *= c1;
            }
        }
        __syncthreads();
        if (tid < 128) {
            float s2 = red[tid * 4 + 0] + red[tid * 4 + 1] + red[tid * 4 + 2] + red[tid * 4 + 3];
            lrow[tid] = lrow[tid] * crow[tid] + s2;
        }

        // ---- O += P @ V ----
#pragma unroll
        for (int ks = 0; ks < 16; ++ks) {
            int k = ks * 8;
            unsigned a[4][4], b[2][2];
#pragma unroll
            for (int mi = 0; mi < 4; mi++) {
                int rb = wm * 64 + mi * 16;
                a[mi][0] = __float_as_uint(P_s[(rb + g) * P_LD + k + l4]);
                a[mi][1] = __float_as_uint(P_s[(rb + g + 8) * P_LD + k + l4]);
                a[mi][2] = __float_as_uint(P_s[(rb + g) * P_LD + k + l4 + 4]);
                a[mi][3] = __float_as_uint(P_s[(rb + g + 8) * P_LD + k + l4 + 4]);
            }
#pragma unroll
            for (int ni = 0; ni < 2; ni++) {
                int cb = wn * 16 + ni * 8;
                b[ni][0] = __float_as_uint(V_s[(k + l4) * QK_LD + cb + g]);
                b[ni][1] = __float_as_uint(V_s[(k + l4 + 4) * QK_LD + cb + g]);
            }
#pragma unroll
            for (int mi = 0; mi < 4; mi++)
#pragma unroll
                for (int ni = 0; ni < 2; ni++)
                    mma_tf32(o[mi][ni], a[mi], b[ni]);
        }
        __syncthreads();
    }

    // epilogue: divide by lrow, write out (tf32-rounded: feeds Wo GEMM)
#pragma unroll
    for (int mi = 0; mi < 4; mi++) {
        int r0 = wm * 64 + mi * 16 + g;
        int r1 = r0 + 8;
        float li0 = 1.f / lrow[r0];
        float li1 = 1.f / lrow[r1];
#pragma unroll
        for (int ni = 0; ni < 2; ni++) {
            int c = wn * 16 + ni * 8 + l4 * 2;
            float2 v0 = {f2tf32f(o[mi][ni][0] * li0), f2tf32f(o[mi][ni][1] * li0)};
            float2 v1 = {f2tf32f(o[mi][ni][2] * li1), f2tf32f(o[mi][ni][3] * li1)};
            *(float2*)(Og + baseQ + (size_t)r0 * DMODEL + c) = v0;
            *(float2*)(Og + baseQ + (size_t)r1 * DMODEL + c) = v1;
        }
    }
}

// ---------------- pipelined tf32 GEMM: C[M,N] = A[M,K] @ B[N,K]^T + bias ----------------
// A and B must already be tf32-rounded. 3-stage cp.async pipeline, 128x128x32 tiles.
#define G_LD 36
#define G_STG (128 * G_LD)

__device__ __forceinline__ void load_frags(
    const float* __restrict__ As, const float* __restrict__ Bs, int k,
    int wm, int wn, int g, int l4,
    unsigned a[4][4], unsigned b[4][2])
{
#pragma unroll
    for (int mi = 0; mi < 4; mi++) {
        int rb = wm * 64 + mi * 16;
        a[mi][0] = __float_as_uint(As[(rb + g) * G_LD + k + l4]);
        a[mi][1] = __float_as_uint(As[(rb + g + 8) * G_LD + k + l4]);
        a[mi][2] = __float_as_uint(As[(rb + g) * G_LD + k + l4 + 4]);
        a[mi][3] = __float_as_uint(As[(rb + g + 8) * G_LD + k + l4 + 4]);
    }
#pragma unroll
    for (int ni = 0; ni < 4; ni++) {
        int nb = wn * 32 + ni * 8;
        b[ni][0] = __float_as_uint(Bs[(nb + g) * G_LD + k + l4]);
        b[ni][1] = __float_as_uint(Bs[(nb + g) * G_LD + k + l4 + 4]);
    }
}

template <bool RELU, bool ROUND_OUT>
__global__ __launch_bounds__(256) void sgemm_tf32_pipe(
    const float* __restrict__ A, const float* __restrict__ B,
    const float* __restrict__ bias, float* __restrict__ C,
    int M, int N, int K)
{
    extern __shared__ float smem[];   // 3 stages x (A tile + B tile)
    int tid = threadIdx.x;
    int warp = tid >> 5, lane = tid & 31;
    int g = lane >> 2, l4 = lane & 3;
    int wm = warp >> 2, wn = warp & 3;
    int n0 = blockIdx.x * 128, m0 = blockIdx.y * 128;

    int crow = tid >> 3;          // 0..31
    int ccol = (tid & 7) * 4;     // 0,4,..28

    const float* Abase = A + (size_t)m0 * K;
    const float* Bbase = B + (size_t)n0 * K;

    auto issue = [&](int s, int kb) {
        float* As = smem + s * 2 * G_STG;
        float* Bs = As + G_STG;
#pragma unroll
        for (int it = 0; it < 4; ++it) {
            int row = crow + it * 32;
            uint32_t da = (uint32_t)__cvta_generic_to_shared(&As[row * G_LD + ccol]);
            cp_async16(da, Abase + (size_t)row * K + kb + ccol);
            uint32_t db = (uint32_t)__cvta_generic_to_shared(&Bs[row * G_LD + ccol]);
            cp_async16(db, Bbase + (size_t)row * K + kb + ccol);
        }
    };

    float acc[4][4][4];
#pragma unroll
    for (int mi = 0; mi < 4; mi++)
#pragma unroll
        for (int ni = 0; ni < 4; ni++)
#pragma unroll
            for (int j = 0; j < 4; j++) acc[mi][ni][j] = 0.f;

    int nt = K >> 5;
    issue(0, 0);  cp_commit();
    issue(1, 32); cp_commit();
    cp_wait<1>();
    __syncthreads();

    for (int t = 0; t < nt; ++t) {
        int st = t % 3;
        if (t + 2 < nt) { issue((t + 2) % 3, (t + 2) * 32); cp_commit(); }

        const float* As = smem + st * 2 * G_STG;
        const float* Bs = As + G_STG;

        unsigned afr[2][4][4], bfr[2][4][2];
        load_frags(As, Bs, 0, wm, wn, g, l4, afr[0], bfr[0]);
#pragma unroll
        for (int ks = 0; ks < 4; ++ks) {
            if (ks < 3)
                load_frags(As, Bs, (ks + 1) * 8, wm, wn, g, l4,
                           afr[(ks + 1) & 1], bfr[(ks + 1) & 1]);
#pragma unroll
            for (int mi = 0; mi < 4; mi++)
#pragma unroll
                for (int ni = 0; ni < 4; ni++)
                    mma_tf32(acc[mi][ni], afr[ks & 1][mi], bfr[ks & 1][ni]);
        }

        if (t + 2 < nt) cp_wait<1>();
        else            cp_wait<0>();
        __syncthreads();
    }

    // epilogue
#pragma unroll
    for (int ni = 0; ni < 4; ni++) {
        int c = n0 + wn * 32 + ni * 8 + l4 * 2;
        float b0 = bias[c], b1 = bias[c + 1];
#pragma unroll
        for (int mi = 0; mi < 4; mi++) {
            int r0 = m0 + wm * 64 + mi * 16 + g;
            int r1 = r0 + 8;
            float2 v0 = {acc[mi][ni][0] + b0, acc[mi][ni][1] + b1};
            float2 v1 = {acc[mi][ni][2] + b0, acc[mi][ni][3] + b1};
            if (RELU) {
                v0.x = fmaxf(v0.x, 0.f); v0.y = fmaxf(v0.y, 0.f);
                v1.x = fmaxf(v1.x, 0.f); v1.y = fmaxf(v1.y, 0.f);
            }
            if (ROUND_OUT) {
                v0.x = f2tf32f(v0.x); v0.y = f2tf32f(v0.y);
                v1.x = f2tf32f(v1.x); v1.y = f2tf32f(v1.y);
            }
            *(float2*)(C + (size_t)r0 * N + c) = v0;
            *(float2*)(C + (size_t)r1 * N + c) = v1;
        }
    }
}

// ---------------- fused residual-add + LayerNorm (+ optional tf32 copy) ----------------
__global__ __launch_bounds__(128) void add_ln_kernel(
    const float* __restrict__ x, const float* __restrict__ a,
    const float* __restrict__ g, const float* __restrict__ b,
    float* __restrict__ dst, float* __restrict__ dst_tf)
{
    int t = blockIdx.x, tid = threadIdx.x;
    float4 v  = ((const float4*)(x + (size_t)t * DMODEL))[tid];
    float4 av = ((const float4*)(a + (size_t)t * DMODEL))[tid];
    v.x += av.x; v.y += av.y; v.z += av.z; v.w += av.w;
    float s  = v.x + v.y + v.z + v.w;
    float sq = v.x * v.x + v.y * v.y + v.z * v.z + v.w * v.w;
#pragma unroll
    for (int o = 16; o > 0; o >>= 1) {
        s  += __shfl_xor_sync(0xffffffffu, s,  o);
        sq += __shfl_xor_sync(0xffffffffu, sq, o);
    }
    __shared__ float ws[4], wq[4];
    int warp = tid >> 5, lane = tid & 31;
    if (lane == 0) { ws[warp] = s; wq[warp] = sq; }
    __syncthreads();
    s  = ws[0] + ws[1] + ws[2] + ws[3];
    sq = wq[0] + wq[1] + wq[2] + wq[3];
    float mean = s * (1.f / 512.f);
    float var  = sq * (1.f / 512.f) - mean * mean;
    float rs = rsqrtf(var + 1e-5f);
    float4 gg  = ((const float4*)g)[tid];
    float4 bb2 = ((const float4*)b)[tid];
    float4 o4;
    o4.x = (v.x - mean) * rs * gg.x + bb2.x;
    o4.y = (v.y - mean) * rs * gg.y + bb2.y;
    o4.z = (v.z - mean) * rs * gg.z + bb2.z;
    o4.w = (v.w - mean) * rs * gg.w + bb2.w;
    ((float4*)(dst + (size_t)t * DMODEL))[tid] = o4;
    if (dst_tf) {
        float4 r4;
        r4.x = f2tf32f(o4.x); r4.y = f2tf32f(o4.y);
        r4.z = f2tf32f(o4.z); r4.w = f2tf32f(o4.w);
        ((float4*)(dst_tf + (size_t)t * DMODEL))[tid] = r4;
    }
}

// ---------------- launcher ----------------
extern "C" void kernel_launch(void* const* d_in, const int* in_sizes, int n_in,
                              void* d_out, int out_size)
{
    const int*   src  = (const int*)d_in[0];
    const int*   mask = (const int*)d_in[1];
    const float* emb = (const float*)d_in[2];
    const float* Wq  = (const float*)d_in[3];
    const float* bq  = (const float*)d_in[4];
    const float* Wk  = (const float*)d_in[5];
    const float* bk  = (const float*)d_in[6];
    const float* Wv  = (const float*)d_in[7];
    const float* bv  = (const float*)d_in[8];
    const float* Wo  = (const float*)d_in[9];
    const float* bo  = (const float*)d_in[10];
    const float* W1  = (const float*)d_in[11];
    const float* b1  = (const float*)d_in[12];
    const float* W2  = (const float*)d_in[13];
    const float* b2  = (const float*)d_in[14];
    const float* ln1g = (const float*)d_in[15];
    const float* ln1b = (const float*)d_in[16];
    const float* ln2g = (const float*)d_in[17];
    const float* ln2b = (const float*)d_in[18];
    float* out = (float*)d_out;

    float *h, *htf, *q, *k, *v, *att, *proj, *ff, *woT, *w1T, *w2T;
    cudaGetSymbolAddress((void**)&h,    g_h);
    cudaGetSymbolAddress((void**)&htf,  g_htf);
    cudaGetSymbolAddress((void**)&q,    g_q);
    cudaGetSymbolAddress((void**)&k,    g_k);
    cudaGetSymbolAddress((void**)&v,    g_v);
    cudaGetSymbolAddress((void**)&att,  g_att);
    cudaGetSymbolAddress((void**)&proj, g_proj);
    cudaGetSymbolAddress((void**)&ff,   g_ff);
    cudaGetSymbolAddress((void**)&woT,  g_wo_t);
    cudaGetSymbolAddress((void**)&w1T,  g_w1_t);
    cudaGetSymbolAddress((void**)&w2T,  g_w2_t);

    const size_t flashSmem = (size_t)(3 * 128 * QK_LD + 128 * P_LD + 3 * 128 + 512 + 128)
                             * sizeof(float);
    cudaFuncSetAttribute(flash_kernel, cudaFuncAttributeMaxDynamicSharedMemorySize,
                         (int)flashSmem);
    const size_t gemmSmem = (size_t)3 * 2 * G_STG * sizeof(float);   // 110,592 B
    cudaFuncSetAttribute(sgemm_tf32_pipe<false, false>,
                         cudaFuncAttributeMaxDynamicSharedMemorySize, (int)gemmSmem);
    cudaFuncSetAttribute(sgemm_tf32_pipe<true, true>,
                         cudaFuncAttributeMaxDynamicSharedMemorySize, (int)gemmSmem);

    // pre-round all GEMM weights to tf32 (graph-captured; deterministic)
    {
        int n4;
        n4 = NLAYER * DMODEL * DMODEL / 4;
        round_tf32_kernel<<<(n4 + 255) / 256, 256>>>((const float4*)Wo, (float4*)woT, n4);
        n4 = NLAYER * FDIM * DMODEL / 4;
        round_tf32_kernel<<<(n4 + 255) / 256, 256>>>((const float4*)W1, (float4*)w1T, n4);
        round_tf32_kernel<<<(n4 + 255) / 256, 256>>>((const float4*)W2, (float4*)w2T, n4);
    }

    embed_kernel<<<T_TOK, 128>>>(src, emb, h);

    for (int l = 0; l < NLAYER; ++l) {
        qkv_kernel<<<256, 128>>>(h,
            Wq + (size_t)l * HDIM * HDIM, Wk + (size_t)l * HDIM * HDIM, Wv + (size_t)l * HDIM * HDIM,
            bq + l * HDIM, bk + l * HDIM, bv + l * HDIM,
            q, k, v);

        flash_kernel<<<dim3(16, NHEAD, 2), 256, flashSmem>>>(q, k, v, mask, att);

        sgemm_tf32_pipe<false, false><<<dim3(4, 32), 256, gemmSmem>>>(
            att, woT + (size_t)l * DMODEL * DMODEL, bo + l * DMODEL, proj,
            T_TOK, DMODEL, DMODEL);

        add_ln_kernel<<<T_TOK, 128>>>(h, proj, ln1g + l * DMODEL, ln1b + l * DMODEL,
                                      h, htf);

        sgemm_tf32_pipe<true, true><<<dim3(16, 32), 256, gemmSmem>>>(
            htf, w1T + (size_t)l * FDIM * DMODEL, b1 + l * FDIM, ff,
            T_TOK, FDIM, DMODEL);

        sgemm_tf32_pipe<false, false><<<dim3(4, 32), 256, gemmSmem>>>(
            ff, w2T + (size_t)l * DMODEL * FDIM, b2 + l * DMODEL, proj,
            T_TOK, DMODEL, FDIM);

        add_ln_kernel<<<T_TOK, 128>>>(h, proj, ln2g + l * DMODEL, ln2b + l * DMODEL,
                                      (l == NLAYER - 1) ? out : h, (float*)nullptr);
    }
}